// round 16
// baseline (speedup 1.0000x reference)
#include <cuda_runtime.h>
#include <cuda_bf16.h>
#include <float.h>
#include <limits.h>
#include <stdint.h>

// VectorQuantizerEMA forward (eval mode).
//   d_in[0] = X [65536, 256] f32,  d_in[1] = E [1024, 256] f32
//   out (f32): [quantized_st 16777216 | loss 1 | indices 65536]
//
// Phase 1: SINGLE-PASS bf16 scoring GEMM on mma.sync m16n8k16 (native on
//   sm_103). ||e||^2 folded via 2 augmented K-cols. Lane-local top-6 -> 24
//   disjoint candidates/row. Occupancy 2 (R14, latency-bound confirmed);
//   X staging smem reused as E buffer B.
// Phase 2: warp-per-row coalesced rescore, 4-way candidate ILP (R15) ->
//   top-2; exact fp64 on the 2 finalists.
//   R16: EPILOGUE FUSED here -- the winning E row and the X row are already
//   in registers after the finalist pass, so q/loss/index are produced and
//   written directly (identical fp32 element math; old epilogue deleted,
//   saving a full X re-read + E re-gather + 64-iter loop).
//
// NOTE: harness compiles at compute_103 (no 'a'): tcgen05/TMEM unavailable;
// fp16.f32 mma is ptxas-emulated ~13x slower than bf16 (measured R10/R11).

#define NROWS    65536
#define DDIM     256
#define KAUG     272               // 256 + 16 (cols 256/257: -|e|^2/2 cascade)
#define KSTEPS   (KAUG / 16)       // 17
#define KCODES   1024
#define M_TILE   128
#define THREADS  256
#define WARPS    8
#define CCHUNK   32                // codes per smem chunk
#define NCHUNKS  (KCODES / CCHUNK) // 32
#define ESTRIDE  560               // bytes/row: 280 bf16 (272 used + pad)
#define X_BYTES  (M_TILE * ESTRIDE)       // 71680
#define ECH      (CCHUNK * ESTRIDE)       // 17920 per chunk
// E buffers alternate: bufA at X_BYTES (always free), bufB at 0 (X region,
// free after A-fragments are in registers). chunk c -> (c&1) ? 0 : X_BYTES.
#define DYN_SMEM (X_BYTES + ECH)          // 89600 -> occ=2

__device__ double g_loss_accum;
__device__ __align__(16) unsigned char g_Ebf[KCODES * ESTRIDE];  // 573 KB

// ---------------------------------------------------------------------------
__device__ __forceinline__ uint32_t smem_u32(const void* p) {
    uint32_t a;
    asm("{ .reg .u64 t; cvta.to.shared.u64 t, %1; cvt.u32.u64 %0, t; }"
        : "=r"(a) : "l"(p));
    return a;
}
__device__ __forceinline__ void ldmatrix_x4(uint32_t& r0, uint32_t& r1,
                                            uint32_t& r2, uint32_t& r3,
                                            uint32_t addr) {
    asm volatile("ldmatrix.sync.aligned.m8n8.x4.shared.b16 {%0,%1,%2,%3}, [%4];"
                 : "=r"(r0), "=r"(r1), "=r"(r2), "=r"(r3) : "r"(addr));
}
__device__ __forceinline__ void mma4(float c[4], const uint32_t a[4],
                                     uint32_t b0, uint32_t b1) {
    asm volatile(
        "mma.sync.aligned.m16n8k16.row.col.f32.bf16.bf16.f32 "
        "{%0,%1,%2,%3}, {%4,%5,%6,%7}, {%8,%9}, {%0,%1,%2,%3};"
        : "+f"(c[0]), "+f"(c[1]), "+f"(c[2]), "+f"(c[3])
        : "r"(a[0]), "r"(a[1]), "r"(a[2]), "r"(a[3]), "r"(b0), "r"(b1));
}
#define CP16(dst, src) \
    asm volatile("cp.async.cg.shared.global [%0], [%1], 16;" \
                 :: "r"(dst), "l"(src) : "memory")
#define CP_COMMIT() asm volatile("cp.async.commit_group;" ::: "memory")
#define CP_WAIT(n)  asm volatile("cp.async.wait_group %0;" :: "n"(n) : "memory")

// sorted top-6 by score desc (constant-index nested ifs -> predicated
// selects, register resident; NO loops/returns). Strict '>' only: in-lane
// codes ascend, so ties keep the earlier code.
__device__ __forceinline__ void ins6(float s, int c, float v[6], int ix[6]) {
    if (s > v[5]) {
        if (s > v[4]) {
            v[5] = v[4]; ix[5] = ix[4];
            if (s > v[3]) {
                v[4] = v[3]; ix[4] = ix[3];
                if (s > v[2]) {
                    v[3] = v[2]; ix[3] = ix[2];
                    if (s > v[1]) {
                        v[2] = v[1]; ix[2] = ix[1];
                        if (s > v[0]) {
                            v[1] = v[0]; ix[1] = ix[0]; v[0] = s; ix[0] = c;
                        } else { v[1] = s; ix[1] = c; }
                    } else { v[2] = s; ix[2] = c; }
                } else { v[3] = s; ix[3] = c; }
            } else { v[4] = s; ix[4] = c; }
        } else { v[5] = s; ix[5] = c; }
    }
}

// top-2 (min) update; ties -> lower code index
__device__ __forceinline__ void top2min(float dd, int cand,
                                        float& v1, int& i1,
                                        float& v2, int& i2) {
    if (dd < v1 || (dd == v1 && cand < i1)) {
        v2 = v1; i2 = i1; v1 = dd; i1 = cand;
    } else if (dd < v2 || (dd == v2 && cand < i2)) {
        v2 = dd; i2 = cand;
    }
}

// ---------------------------------------------------------------------------
// prep: E -> bf16 rows of 280 (272 used); aug cols 256/257 carry a 2-term
// bf16 cascade of -|e|^2/2. One warp per code.
// ---------------------------------------------------------------------------
__global__ void vq_prep(const float* __restrict__ E) {
    const int w = threadIdx.x >> 5, lane = threadIdx.x & 31;
    const int code = blockIdx.x * 8 + w;
    if (blockIdx.x == 0 && threadIdx.x == 0) g_loss_accum = 0.0;

    const float4* e4 = reinterpret_cast<const float4*>(E + (size_t)code * DDIM);
    float4 va = e4[lane * 2], vb = e4[lane * 2 + 1];

    __nv_bfloat162 p0 = __floats2bfloat162_rn(va.x, va.y);
    __nv_bfloat162 p1 = __floats2bfloat162_rn(va.z, va.w);
    __nv_bfloat162 p2 = __floats2bfloat162_rn(vb.x, vb.y);
    __nv_bfloat162 p3 = __floats2bfloat162_rn(vb.z, vb.w);
    uint4 out;
    out.x = *reinterpret_cast<uint32_t*>(&p0);
    out.y = *reinterpret_cast<uint32_t*>(&p1);
    out.z = *reinterpret_cast<uint32_t*>(&p2);
    out.w = *reinterpret_cast<uint32_t*>(&p3);
    *reinterpret_cast<uint4*>(g_Ebf + (size_t)code * ESTRIDE + lane * 16) = out;

    double s = 0.0;
    s += (double)va.x * va.x; s += (double)va.y * va.y;
    s += (double)va.z * va.z; s += (double)va.w * va.w;
    s += (double)vb.x * vb.x; s += (double)vb.y * vb.y;
    s += (double)vb.z * vb.z; s += (double)vb.w * vb.w;
#pragma unroll
    for (int o = 16; o >= 1; o >>= 1)
        s += __shfl_xor_sync(0xffffffffu, s, o);

    if (lane == 0) {
        double d = -0.5 * s;
        __nv_bfloat16 h1 = __float2bfloat16_rn((float)d);
        d -= (double)__bfloat162float(h1);
        __nv_bfloat16 h2 = __float2bfloat16_rn((float)d);
        uint32_t w0 = (uint32_t)*reinterpret_cast<unsigned short*>(&h1) |
                      ((uint32_t)*reinterpret_cast<unsigned short*>(&h2) << 16);
        unsigned char* b = g_Ebf + (size_t)code * ESTRIDE + 512;
        *reinterpret_cast<uint4*>(b +  0) = make_uint4(w0, 0u, 0u, 0u);
        *reinterpret_cast<uint4*>(b + 16) = make_uint4(0u, 0u, 0u, 0u);
        *reinterpret_cast<uint4*>(b + 32) = make_uint4(0u, 0u, 0u, 0u);
    }
}

// ---------------------------------------------------------------------------
__device__ __forceinline__ void prefetch_chunk(uint32_t dst, int chunk, int tid) {
    const unsigned char* src = g_Ebf + (size_t)chunk * ECH;
#pragma unroll 1
    for (int i = tid; i < ECH / 16; i += THREADS)
        CP16(dst + (uint32_t)i * 16u, src + (size_t)i * 16);
    CP_COMMIT();
}

// ---------------------------------------------------------------------------
// main: 512 CTAs x 256 threads (8 warps), occ=2; warp w owns rows w*16..+15.
// ---------------------------------------------------------------------------
__global__ __launch_bounds__(THREADS, 2)
void vq_main_mma(const float* __restrict__ X, const float* __restrict__ E,
                 float* __restrict__ outQ, float* __restrict__ outIdx) {
    extern __shared__ __align__(16) unsigned char sm[];
    __shared__ int   sCand[M_TILE][24];
    __shared__ float sRed[WARPS];

    const int tid  = threadIdx.x;
    const int w    = tid >> 5;
    const int lane = tid & 31;
    const int rowbase = blockIdx.x * M_TILE;

    const uint32_t sm_u = smem_u32(sm);

    // chunk 0 -> bufA (beyond the X region; disjoint from X staging)
    prefetch_chunk(sm_u + X_BYTES, 0, tid);

    // ---- stage X tile: f32 -> bf16 rows of 280 + aug cols (1.0, 1.0) ------
    for (int i = tid; i < M_TILE * 3; i += THREADS) {
        int r = i / 3, part = i % 3;
        uint4 val = (part == 0) ? make_uint4(0x3F803F80u, 0u, 0u, 0u)
                                : make_uint4(0u, 0u, 0u, 0u);
        *reinterpret_cast<uint4*>(sm + r * ESTRIDE + 512 + part * 16) = val;
    }
    {
        const float4* xg = reinterpret_cast<const float4*>(X + (size_t)rowbase * DDIM);
        for (int i = tid; i < M_TILE * (DDIM / 4); i += THREADS) {
            int r = i >> 6, c4 = i & 63;
            float4 v = xg[i];
            __nv_bfloat162 q0 = __floats2bfloat162_rn(v.x, v.y);
            __nv_bfloat162 q1 = __floats2bfloat162_rn(v.z, v.w);
            uint2 o;
            o.x = *reinterpret_cast<uint32_t*>(&q0);
            o.y = *reinterpret_cast<uint32_t*>(&q1);
            *reinterpret_cast<uint2*>(sm + r * ESTRIDE + c4 * 8) = o;
        }
    }
    __syncthreads();

    // ---- register-resident A fragments (17 ksteps x 4 regs) ---------------
    uint32_t ah[KSTEPS][4];
    {
        uint32_t off = (uint32_t)(w * 16 + (lane & 15)) * ESTRIDE +
                       (uint32_t)((lane >> 4) * 16);
#pragma unroll
        for (int s = 0; s < KSTEPS; ++s)
            ldmatrix_x4(ah[s][0], ah[s][1], ah[s][2], ah[s][3],
                        sm_u + off + s * 32);
    }
    __syncthreads();   // ALL warps done reading X -> region 0 becomes bufB

    // chunk 1 -> bufB (the freed X region)
    prefetch_chunk(sm_u, 1, tid);

    // ---- score all codes; lane-local top-6 for rows (A, A+8) --------------
    float vA[6] = {-FLT_MAX, -FLT_MAX, -FLT_MAX, -FLT_MAX, -FLT_MAX, -FLT_MAX};
    float vB[6] = {-FLT_MAX, -FLT_MAX, -FLT_MAX, -FLT_MAX, -FLT_MAX, -FLT_MAX};
    int ixA[6] = {INT_MAX, INT_MAX, INT_MAX, INT_MAX, INT_MAX, INT_MAX};
    int ixB[6] = {INT_MAX, INT_MAX, INT_MAX, INT_MAX, INT_MAX, INT_MAX};

    // ldmatrix.x4 B address (validated R10-R15): matrices {tile k0-7,
    // tile k8-15, tile+1 k0-7, tile+1 k8-15}.
    const uint32_t brow4 = (uint32_t)(lane & 7) * ESTRIDE +
                           (uint32_t)(((lane >> 3) & 1) * 16) +
                           (uint32_t)((lane >> 4) * 8) * ESTRIDE;

    for (int chunk = 0; chunk < NCHUNKS; ++chunk) {
        const uint32_t buf = sm_u + ((chunk & 1) ? 0u : (uint32_t)X_BYTES);
        if (chunk == NCHUNKS - 1) { CP_WAIT(0); } else { CP_WAIT(1); }
        __syncthreads();

        // 4 n-tiles of 8 codes, 4 independent accumulator chains
        float ac0[4] = {0.f, 0.f, 0.f, 0.f}, ac1[4] = {0.f, 0.f, 0.f, 0.f};
        float ac2[4] = {0.f, 0.f, 0.f, 0.f}, ac3[4] = {0.f, 0.f, 0.f, 0.f};
        const uint32_t b01 = buf + brow4;              // tiles 0,1
        const uint32_t b23 = b01 + 16u * ESTRIDE;      // tiles 2,3
#pragma unroll
        for (int s = 0; s < KSTEPS; ++s) {
            uint32_t b00, b01r, b10, b11, b20, b21, b30, b31;
            ldmatrix_x4(b00, b01r, b10, b11, b01 + s * 32);
            ldmatrix_x4(b20, b21,  b30, b31, b23 + s * 32);
            mma4(ac0, ah[s], b00, b01r);
            mma4(ac1, ah[s], b10, b11);
            mma4(ac2, ah[s], b20, b21);
            mma4(ac3, ah[s], b30, b31);
        }
        const int cb = chunk * CCHUNK + (lane & 3) * 2;
        ins6(ac0[0], cb +  0, vA, ixA); ins6(ac0[1], cb +  1, vA, ixA);
        ins6(ac0[2], cb +  0, vB, ixB); ins6(ac0[3], cb +  1, vB, ixB);
        ins6(ac1[0], cb +  8, vA, ixA); ins6(ac1[1], cb +  9, vA, ixA);
        ins6(ac1[2], cb +  8, vB, ixB); ins6(ac1[3], cb +  9, vB, ixB);
        ins6(ac2[0], cb + 16, vA, ixA); ins6(ac2[1], cb + 17, vA, ixA);
        ins6(ac2[2], cb + 16, vB, ixB); ins6(ac2[3], cb + 17, vB, ixB);
        ins6(ac3[0], cb + 24, vA, ixA); ins6(ac3[1], cb + 25, vA, ixA);
        ins6(ac3[2], cb + 24, vB, ixB); ins6(ac3[3], cb + 25, vB, ixB);
        __syncthreads();              // done reading buf before refill

        if (chunk + 2 < NCHUNKS)
            prefetch_chunk(buf, chunk + 2, tid);   // refill the buffer just freed
    }

    // ---- no cross-lane merge: each lane stores its top-6 (24/row) ---------
    {
        int rA = w * 16 + (lane >> 2);
        int sl = (lane & 3) * 6;
#pragma unroll
        for (int j = 0; j < 6; ++j) {
            sCand[rA][sl + j]     = ixA[j];
            sCand[rA + 8][sl + j] = ixB[j];
        }
    }
    __syncthreads();

    // ---- Phase 2: rescore + FUSED epilogue (warp-per-row) -----------------
    float lsum = 0.0f;   // per-lane loss partial across this warp's 16 rows
    for (int rr = 0; rr < M_TILE / WARPS; ++rr) {
        const int r = w * (M_TILE / WARPS) + rr;
        const float4* x4 = reinterpret_cast<const float4*>(
            X + (size_t)(rowbase + r) * DDIM);
        const float4 xa = x4[lane * 2], xb = x4[lane * 2 + 1];

        float v1 = FLT_MAX, v2 = FLT_MAX;
        int   i1 = INT_MAX, i2 = INT_MAX;
#pragma unroll 1
        for (int c = 0; c < 24; c += 4) {
            const int c0 = sCand[r][c],     c1 = sCand[r][c + 1];
            const int c2 = sCand[r][c + 2], c3 = sCand[r][c + 3];
            const float4* e0 = reinterpret_cast<const float4*>(E + (size_t)c0 * DDIM);
            const float4* e1 = reinterpret_cast<const float4*>(E + (size_t)c1 * DDIM);
            const float4* e2 = reinterpret_cast<const float4*>(E + (size_t)c2 * DDIM);
            const float4* e3 = reinterpret_cast<const float4*>(E + (size_t)c3 * DDIM);
            const float4 e0a = e0[lane * 2], e0b = e0[lane * 2 + 1];
            const float4 e1a = e1[lane * 2], e1b = e1[lane * 2 + 1];
            const float4 e2a = e2[lane * 2], e2b = e2[lane * 2 + 1];
            const float4 e3a = e3[lane * 2], e3b = e3[lane * 2 + 1];
            float d, d0 = 0.f, d1 = 0.f, d2 = 0.f, d3 = 0.f;
            d = xa.x - e0a.x; d0 += d * d;  d = xa.y - e0a.y; d0 += d * d;
            d = xa.z - e0a.z; d0 += d * d;  d = xa.w - e0a.w; d0 += d * d;
            d = xb.x - e0b.x; d0 += d * d;  d = xb.y - e0b.y; d0 += d * d;
            d = xb.z - e0b.z; d0 += d * d;  d = xb.w - e0b.w; d0 += d * d;
            d = xa.x - e1a.x; d1 += d * d;  d = xa.y - e1a.y; d1 += d * d;
            d = xa.z - e1a.z; d1 += d * d;  d = xa.w - e1a.w; d1 += d * d;
            d = xb.x - e1b.x; d1 += d * d;  d = xb.y - e1b.y; d1 += d * d;
            d = xb.z - e1b.z; d1 += d * d;  d = xb.w - e1b.w; d1 += d * d;
            d = xa.x - e2a.x; d2 += d * d;  d = xa.y - e2a.y; d2 += d * d;
            d = xa.z - e2a.z; d2 += d * d;  d = xa.w - e2a.w; d2 += d * d;
            d = xb.x - e2b.x; d2 += d * d;  d = xb.y - e2b.y; d2 += d * d;
            d = xb.z - e2b.z; d2 += d * d;  d = xb.w - e2b.w; d2 += d * d;
            d = xa.x - e3a.x; d3 += d * d;  d = xa.y - e3a.y; d3 += d * d;
            d = xa.z - e3a.z; d3 += d * d;  d = xa.w - e3a.w; d3 += d * d;
            d = xb.x - e3b.x; d3 += d * d;  d = xb.y - e3b.y; d3 += d * d;
            d = xb.z - e3b.z; d3 += d * d;  d = xb.w - e3b.w; d3 += d * d;
            // 4 interleaved butterfly reductions (independent chains)
#pragma unroll
            for (int o = 16; o >= 1; o >>= 1) {
                d0 += __shfl_xor_sync(0xffffffffu, d0, o);
                d1 += __shfl_xor_sync(0xffffffffu, d1, o);
                d2 += __shfl_xor_sync(0xffffffffu, d2, o);
                d3 += __shfl_xor_sync(0xffffffffu, d3, o);
            }
            // sequential top-2 updates in ascending c order (== R14/R15)
            top2min(d0, c0, v1, i1, v2, i2);
            top2min(d1, c1, v1, i1, v2, i2);
            top2min(d2, c2, v1, i1, v2, i2);
            top2min(d3, c3, v1, i1, v2, i2);
        }

        // exact fp64 on the two finalists (coalesced, warp-reduced)
        const float4* ea4 = reinterpret_cast<const float4*>(E + (size_t)i1 * DDIM);
        const float4* eb4 = reinterpret_cast<const float4*>(E + (size_t)i2 * DDIM);
        const float4 a0 = ea4[lane * 2], a1 = ea4[lane * 2 + 1];
        const float4 b0 = eb4[lane * 2], b1 = eb4[lane * 2 + 1];
        double dd, dA = 0.0, dB = 0.0;
        dd = (double)xa.x - (double)a0.x; dA += dd * dd;
        dd = (double)xa.y - (double)a0.y; dA += dd * dd;
        dd = (double)xa.z - (double)a0.z; dA += dd * dd;
        dd = (double)xa.w - (double)a0.w; dA += dd * dd;
        dd = (double)xb.x - (double)a1.x; dA += dd * dd;
        dd = (double)xb.y - (double)a1.y; dA += dd * dd;
        dd = (double)xb.z - (double)a1.z; dA += dd * dd;
        dd = (double)xb.w - (double)a1.w; dA += dd * dd;
        dd = (double)xa.x - (double)b0.x; dB += dd * dd;
        dd = (double)xa.y - (double)b0.y; dB += dd * dd;
        dd = (double)xa.z - (double)b0.z; dB += dd * dd;
        dd = (double)xa.w - (double)b0.w; dB += dd * dd;
        dd = (double)xb.x - (double)b1.x; dB += dd * dd;
        dd = (double)xb.y - (double)b1.y; dB += dd * dd;
        dd = (double)xb.z - (double)b1.z; dB += dd * dd;
        dd = (double)xb.w - (double)b1.w; dB += dd * dd;
#pragma unroll
        for (int o = 16; o >= 1; o >>= 1) {
            dA += __shfl_xor_sync(0xffffffffu, dA, o);
            dB += __shfl_xor_sync(0xffffffffu, dB, o);
        }
        const bool firstWins = (dA < dB || (dA == dB && i1 < i2));
        const int win = firstWins ? i1 : i2;

        // ---- fused epilogue: winner's e already in registers --------------
        const float4 ea = firstWins ? a0 : b0;
        const float4 eb = firstWins ? a1 : b1;
        float4 dv, qv;
        float* outRow = outQ + (size_t)(rowbase + r) * DDIM;
        dv.x = ea.x - xa.x; dv.y = ea.y - xa.y;
        dv.z = ea.z - xa.z; dv.w = ea.w - xa.w;
        qv.x = xa.x + dv.x; qv.y = xa.y + dv.y;
        qv.z = xa.z + dv.z; qv.w = xa.w + dv.w;
        lsum += dv.x * dv.x + dv.y * dv.y + dv.z * dv.z + dv.w * dv.w;
        reinterpret_cast<float4*>(outRow)[lane * 2] = qv;
        dv.x = eb.x - xb.x; dv.y = eb.y - xb.y;
        dv.z = eb.z - xb.z; dv.w = eb.w - xb.w;
        qv.x = xb.x + dv.x; qv.y = xb.y + dv.y;
        qv.z = xb.z + dv.z; qv.w = xb.w + dv.w;
        lsum += dv.x * dv.x + dv.y * dv.y + dv.z * dv.z + dv.w * dv.w;
        reinterpret_cast<float4*>(outRow)[lane * 2 + 1] = qv;
        if (lane == 0) outIdx[rowbase + r] = (float)win;
    }

    // ---- loss: warp-reduce lane partials, one double atomic per CTA -------
#pragma unroll
    for (int s = 16; s >= 1; s >>= 1)
        lsum += __shfl_xor_sync(0xffffffffu, lsum, s);
    if (lane == 0) sRed[w] = lsum;
    __syncthreads();
    if (tid == 0) {
        float s = 0.0f;
#pragma unroll
        for (int i = 0; i < WARPS; ++i) s += sRed[i];
        atomicAdd(&g_loss_accum, (double)s);
    }
}

// ---------------------------------------------------------------------------
__global__ void vq_finalize(float* __restrict__ outLoss) {
    if (threadIdx.x == 0)
        *outLoss = (float)(g_loss_accum * (1.0 / (double)((size_t)NROWS * DDIM)));
}

// ---------------------------------------------------------------------------
extern "C" void kernel_launch(void* const* d_in, const int* in_sizes, int n_in,
                              void* d_out, int out_size) {
    (void)in_sizes; (void)n_in; (void)out_size;
    const float* X = (const float*)d_in[0];
    const float* E = (const float*)d_in[1];

    float* outQ    = (float*)d_out;
    float* outLoss = outQ + (size_t)NROWS * DDIM;   // 16777216
    float* outIdx  = outLoss + 1;                   // 16777217

    cudaFuncSetAttribute(vq_main_mma, cudaFuncAttributeMaxDynamicSharedMemorySize,
                         DYN_SMEM);

    vq_prep<<<KCODES / 8, 256>>>(E);
    vq_main_mma<<<NROWS / M_TILE, THREADS, DYN_SMEM>>>(X, E, outQ, outIdx);
    vq_finalize<<<1, 32>>>(outLoss);
}

// round 17
// speedup vs baseline: 1.1487x; 1.1487x over previous
#include <cuda_runtime.h>
#include <cuda_bf16.h>
#include <float.h>
#include <limits.h>
#include <stdint.h>

// VectorQuantizerEMA forward (eval mode).
//   d_in[0] = X [65536, 256] f32,  d_in[1] = E [1024, 256] f32
//   out (f32): [quantized_st 16777216 | loss 1 | indices 65536]
//
// Phase 1: SINGLE-PASS bf16 scoring GEMM on mma.sync m16n8k16 (native on
//   sm_103). ||e||^2 folded via 2 augmented K-cols. Lane-local top-6 -> 24
//   disjoint candidates/row, stored PACKED (bf16(score)<<16 | code).
//   Occupancy 2 (R14); X staging smem reused as E buffer B.
// Phase 2 (R17): PROXY-MARGIN PRUNED rescore -- candidates with proxy score
//   < rowmax - 1.5 (~7 sigma of proxy+packing noise) are skipped; ~1.6
//   survive per row on average, cutting the rescore's ~125us of L2 traffic
//   ~15x. Survivors get the fp32 coalesced rescore -> top-2; exact fp64 on
//   the 2 finalists (i2:=i1 fallback if only one survives).
// Epilogue: R15's separate striped epilogue (R16's fused variant regressed).
//
// NOTE: harness compiles at compute_103 (no 'a'): tcgen05/TMEM unavailable;
// fp16.f32 mma is ptxas-emulated ~13x slower than bf16 (measured R10/R11).

#define NROWS    65536
#define DDIM     256
#define KAUG     272               // 256 + 16 (cols 256/257: -|e|^2/2 cascade)
#define KSTEPS   (KAUG / 16)       // 17
#define KCODES   1024
#define M_TILE   128
#define THREADS  256
#define WARPS    8
#define CCHUNK   32                // codes per smem chunk
#define NCHUNKS  (KCODES / CCHUNK) // 32
#define ESTRIDE  560               // bytes/row: 280 bf16 (272 used + pad)
#define X_BYTES  (M_TILE * ESTRIDE)       // 71680
#define ECH      (CCHUNK * ESTRIDE)       // 17920 per chunk
// E buffers alternate: bufA at X_BYTES, bufB at 0 (X region, free after
// A-fragments are in registers). chunk c -> (c&1) ? 0 : X_BYTES.
#define DYN_SMEM (X_BYTES + ECH)          // 89600 -> occ=2
#define MARGIN   1.5f              // proxy-score pruning margin (~7 sigma)

__device__ double g_loss_accum;
__device__ __align__(16) unsigned char g_Ebf[KCODES * ESTRIDE];  // 573 KB

// ---------------------------------------------------------------------------
__device__ __forceinline__ uint32_t smem_u32(const void* p) {
    uint32_t a;
    asm("{ .reg .u64 t; cvta.to.shared.u64 t, %1; cvt.u32.u64 %0, t; }"
        : "=r"(a) : "l"(p));
    return a;
}
__device__ __forceinline__ void ldmatrix_x4(uint32_t& r0, uint32_t& r1,
                                            uint32_t& r2, uint32_t& r3,
                                            uint32_t addr) {
    asm volatile("ldmatrix.sync.aligned.m8n8.x4.shared.b16 {%0,%1,%2,%3}, [%4];"
                 : "=r"(r0), "=r"(r1), "=r"(r2), "=r"(r3) : "r"(addr));
}
__device__ __forceinline__ void mma4(float c[4], const uint32_t a[4],
                                     uint32_t b0, uint32_t b1) {
    asm volatile(
        "mma.sync.aligned.m16n8k16.row.col.f32.bf16.bf16.f32 "
        "{%0,%1,%2,%3}, {%4,%5,%6,%7}, {%8,%9}, {%0,%1,%2,%3};"
        : "+f"(c[0]), "+f"(c[1]), "+f"(c[2]), "+f"(c[3])
        : "r"(a[0]), "r"(a[1]), "r"(a[2]), "r"(a[3]), "r"(b0), "r"(b1));
}
#define CP16(dst, src) \
    asm volatile("cp.async.cg.shared.global [%0], [%1], 16;" \
                 :: "r"(dst), "l"(src) : "memory")
#define CP_COMMIT() asm volatile("cp.async.commit_group;" ::: "memory")
#define CP_WAIT(n)  asm volatile("cp.async.wait_group %0;" :: "n"(n) : "memory")

// sorted top-6 by score desc (constant-index nested ifs, register resident).
// Strict '>' only: in-lane codes ascend, so ties keep the earlier code.
__device__ __forceinline__ void ins6(float s, int c, float v[6], int ix[6]) {
    if (s > v[5]) {
        if (s > v[4]) {
            v[5] = v[4]; ix[5] = ix[4];
            if (s > v[3]) {
                v[4] = v[3]; ix[4] = ix[3];
                if (s > v[2]) {
                    v[3] = v[2]; ix[3] = ix[2];
                    if (s > v[1]) {
                        v[2] = v[1]; ix[2] = ix[1];
                        if (s > v[0]) {
                            v[1] = v[0]; ix[1] = ix[0]; v[0] = s; ix[0] = c;
                        } else { v[1] = s; ix[1] = c; }
                    } else { v[2] = s; ix[2] = c; }
                } else { v[3] = s; ix[3] = c; }
            } else { v[4] = s; ix[4] = c; }
        } else { v[5] = s; ix[5] = c; }
    }
}

// top-2 (min) update; ties -> lower code index
__device__ __forceinline__ void top2min(float dd, int cand,
                                        float& v1, int& i1,
                                        float& v2, int& i2) {
    if (dd < v1 || (dd == v1 && cand < i1)) {
        v2 = v1; i2 = i1; v1 = dd; i1 = cand;
    } else if (dd < v2 || (dd == v2 && cand < i2)) {
        v2 = dd; i2 = cand;
    }
}

// pack (bf16(score) << 16 | code); decode returns bf16-rounded score
__device__ __forceinline__ uint32_t pack_cand(float s, int code) {
    __nv_bfloat16 h = __float2bfloat16_rn(s);
    uint32_t us = (uint32_t)*reinterpret_cast<unsigned short*>(&h);
    return (us << 16) | ((uint32_t)code & 1023u);
}
__device__ __forceinline__ float dec_score(uint32_t pk) {
    return __uint_as_float(pk & 0xFFFF0000u);
}

// ---------------------------------------------------------------------------
// prep: E -> bf16 rows of 280 (272 used); aug cols 256/257 carry a 2-term
// bf16 cascade of -|e|^2/2. One warp per code.
// ---------------------------------------------------------------------------
__global__ void vq_prep(const float* __restrict__ E) {
    const int w = threadIdx.x >> 5, lane = threadIdx.x & 31;
    const int code = blockIdx.x * 8 + w;
    if (blockIdx.x == 0 && threadIdx.x == 0) g_loss_accum = 0.0;

    const float4* e4 = reinterpret_cast<const float4*>(E + (size_t)code * DDIM);
    float4 va = e4[lane * 2], vb = e4[lane * 2 + 1];

    __nv_bfloat162 p0 = __floats2bfloat162_rn(va.x, va.y);
    __nv_bfloat162 p1 = __floats2bfloat162_rn(va.z, va.w);
    __nv_bfloat162 p2 = __floats2bfloat162_rn(vb.x, vb.y);
    __nv_bfloat162 p3 = __floats2bfloat162_rn(vb.z, vb.w);
    uint4 out;
    out.x = *reinterpret_cast<uint32_t*>(&p0);
    out.y = *reinterpret_cast<uint32_t*>(&p1);
    out.z = *reinterpret_cast<uint32_t*>(&p2);
    out.w = *reinterpret_cast<uint32_t*>(&p3);
    *reinterpret_cast<uint4*>(g_Ebf + (size_t)code * ESTRIDE + lane * 16) = out;

    double s = 0.0;
    s += (double)va.x * va.x; s += (double)va.y * va.y;
    s += (double)va.z * va.z; s += (double)va.w * va.w;
    s += (double)vb.x * vb.x; s += (double)vb.y * vb.y;
    s += (double)vb.z * vb.z; s += (double)vb.w * vb.w;
#pragma unroll
    for (int o = 16; o >= 1; o >>= 1)
        s += __shfl_xor_sync(0xffffffffu, s, o);

    if (lane == 0) {
        double d = -0.5 * s;
        __nv_bfloat16 h1 = __float2bfloat16_rn((float)d);
        d -= (double)__bfloat162float(h1);
        __nv_bfloat16 h2 = __float2bfloat16_rn((float)d);
        uint32_t w0 = (uint32_t)*reinterpret_cast<unsigned short*>(&h1) |
                      ((uint32_t)*reinterpret_cast<unsigned short*>(&h2) << 16);
        unsigned char* b = g_Ebf + (size_t)code * ESTRIDE + 512;
        *reinterpret_cast<uint4*>(b +  0) = make_uint4(w0, 0u, 0u, 0u);
        *reinterpret_cast<uint4*>(b + 16) = make_uint4(0u, 0u, 0u, 0u);
        *reinterpret_cast<uint4*>(b + 32) = make_uint4(0u, 0u, 0u, 0u);
    }
}

// ---------------------------------------------------------------------------
__device__ __forceinline__ void prefetch_chunk(uint32_t dst, int chunk, int tid) {
    const unsigned char* src = g_Ebf + (size_t)chunk * ECH;
#pragma unroll 1
    for (int i = tid; i < ECH / 16; i += THREADS)
        CP16(dst + (uint32_t)i * 16u, src + (size_t)i * 16);
    CP_COMMIT();
}

// ---------------------------------------------------------------------------
// main: 512 CTAs x 256 threads (8 warps), occ=2; warp w owns rows w*16..+15.
// ---------------------------------------------------------------------------
__global__ __launch_bounds__(THREADS, 2)
void vq_main_mma(const float* __restrict__ X, const float* __restrict__ E,
                 float* __restrict__ outQ, float* __restrict__ outIdx) {
    extern __shared__ __align__(16) unsigned char sm[];
    __shared__ uint32_t sCand[M_TILE][24];   // packed (bf16 score | code)
    __shared__ float    sRowMax[M_TILE];
    __shared__ int      sWin[M_TILE];
    __shared__ float    sRed[WARPS];

    const int tid  = threadIdx.x;
    const int w    = tid >> 5;
    const int lane = tid & 31;
    const int rowbase = blockIdx.x * M_TILE;

    const uint32_t sm_u = smem_u32(sm);

    // chunk 0 -> bufA (beyond the X region; disjoint from X staging)
    prefetch_chunk(sm_u + X_BYTES, 0, tid);

    // ---- stage X tile: f32 -> bf16 rows of 280 + aug cols (1.0, 1.0) ------
    for (int i = tid; i < M_TILE * 3; i += THREADS) {
        int r = i / 3, part = i % 3;
        uint4 val = (part == 0) ? make_uint4(0x3F803F80u, 0u, 0u, 0u)
                                : make_uint4(0u, 0u, 0u, 0u);
        *reinterpret_cast<uint4*>(sm + r * ESTRIDE + 512 + part * 16) = val;
    }
    {
        const float4* xg = reinterpret_cast<const float4*>(X + (size_t)rowbase * DDIM);
        for (int i = tid; i < M_TILE * (DDIM / 4); i += THREADS) {
            int r = i >> 6, c4 = i & 63;
            float4 v = xg[i];
            __nv_bfloat162 q0 = __floats2bfloat162_rn(v.x, v.y);
            __nv_bfloat162 q1 = __floats2bfloat162_rn(v.z, v.w);
            uint2 o;
            o.x = *reinterpret_cast<uint32_t*>(&q0);
            o.y = *reinterpret_cast<uint32_t*>(&q1);
            *reinterpret_cast<uint2*>(sm + r * ESTRIDE + c4 * 8) = o;
        }
    }
    __syncthreads();

    // ---- register-resident A fragments (17 ksteps x 4 regs) ---------------
    uint32_t ah[KSTEPS][4];
    {
        uint32_t off = (uint32_t)(w * 16 + (lane & 15)) * ESTRIDE +
                       (uint32_t)((lane >> 4) * 16);
#pragma unroll
        for (int s = 0; s < KSTEPS; ++s)
            ldmatrix_x4(ah[s][0], ah[s][1], ah[s][2], ah[s][3],
                        sm_u + off + s * 32);
    }
    __syncthreads();   // ALL warps done reading X -> region 0 becomes bufB

    // chunk 1 -> bufB (the freed X region)
    prefetch_chunk(sm_u, 1, tid);

    // ---- score all codes; lane-local top-6 for rows (A, A+8) --------------
    float vA[6] = {-FLT_MAX, -FLT_MAX, -FLT_MAX, -FLT_MAX, -FLT_MAX, -FLT_MAX};
    float vB[6] = {-FLT_MAX, -FLT_MAX, -FLT_MAX, -FLT_MAX, -FLT_MAX, -FLT_MAX};
    int ixA[6] = {INT_MAX, INT_MAX, INT_MAX, INT_MAX, INT_MAX, INT_MAX};
    int ixB[6] = {INT_MAX, INT_MAX, INT_MAX, INT_MAX, INT_MAX, INT_MAX};

    // ldmatrix.x4 B address (validated R10-R16): matrices {tile k0-7,
    // tile k8-15, tile+1 k0-7, tile+1 k8-15}.
    const uint32_t brow4 = (uint32_t)(lane & 7) * ESTRIDE +
                           (uint32_t)(((lane >> 3) & 1) * 16) +
                           (uint32_t)((lane >> 4) * 8) * ESTRIDE;

    for (int chunk = 0; chunk < NCHUNKS; ++chunk) {
        const uint32_t buf = sm_u + ((chunk & 1) ? 0u : (uint32_t)X_BYTES);
        if (chunk == NCHUNKS - 1) { CP_WAIT(0); } else { CP_WAIT(1); }
        __syncthreads();

        // 4 n-tiles of 8 codes, 4 independent accumulator chains
        float ac0[4] = {0.f, 0.f, 0.f, 0.f}, ac1[4] = {0.f, 0.f, 0.f, 0.f};
        float ac2[4] = {0.f, 0.f, 0.f, 0.f}, ac3[4] = {0.f, 0.f, 0.f, 0.f};
        const uint32_t b01 = buf + brow4;              // tiles 0,1
        const uint32_t b23 = b01 + 16u * ESTRIDE;      // tiles 2,3
#pragma unroll
        for (int s = 0; s < KSTEPS; ++s) {
            uint32_t b00, b01r, b10, b11, b20, b21, b30, b31;
            ldmatrix_x4(b00, b01r, b10, b11, b01 + s * 32);
            ldmatrix_x4(b20, b21,  b30, b31, b23 + s * 32);
            mma4(ac0, ah[s], b00, b01r);
            mma4(ac1, ah[s], b10, b11);
            mma4(ac2, ah[s], b20, b21);
            mma4(ac3, ah[s], b30, b31);
        }
        const int cb = chunk * CCHUNK + (lane & 3) * 2;
        ins6(ac0[0], cb +  0, vA, ixA); ins6(ac0[1], cb +  1, vA, ixA);
        ins6(ac0[2], cb +  0, vB, ixB); ins6(ac0[3], cb +  1, vB, ixB);
        ins6(ac1[0], cb +  8, vA, ixA); ins6(ac1[1], cb +  9, vA, ixA);
        ins6(ac1[2], cb +  8, vB, ixB); ins6(ac1[3], cb +  9, vB, ixB);
        ins6(ac2[0], cb + 16, vA, ixA); ins6(ac2[1], cb + 17, vA, ixA);
        ins6(ac2[2], cb + 16, vB, ixB); ins6(ac2[3], cb + 17, vB, ixB);
        ins6(ac3[0], cb + 24, vA, ixA); ins6(ac3[1], cb + 25, vA, ixA);
        ins6(ac3[2], cb + 24, vB, ixB); ins6(ac3[3], cb + 25, vB, ixB);
        __syncthreads();              // done reading buf before refill

        if (chunk + 2 < NCHUNKS)
            prefetch_chunk(buf, chunk + 2, tid);   // refill the buffer just freed
    }

    // ---- store packed top-6 per lane + row proxy max ----------------------
    {
        // row proxy max across the 4 lanes sharing each row (xor 1,2 stay
        // inside the aligned group of 4 lanes)
        float mA = vA[0], mB = vB[0];
#pragma unroll
        for (int o = 1; o <= 2; o <<= 1) {
            mA = fmaxf(mA, __shfl_xor_sync(0xffffffffu, mA, o));
            mB = fmaxf(mB, __shfl_xor_sync(0xffffffffu, mB, o));
        }
        int rA = w * 16 + (lane >> 2);
        int sl = (lane & 3) * 6;
#pragma unroll
        for (int j = 0; j < 6; ++j) {
            sCand[rA][sl + j]     = pack_cand(vA[j], ixA[j]);
            sCand[rA + 8][sl + j] = pack_cand(vB[j], ixB[j]);
        }
        if ((lane & 3) == 0) {
            sRowMax[rA]     = mA;
            sRowMax[rA + 8] = mB;
        }
    }
    __syncthreads();

    // ---- Phase 2: proxy-pruned rescore (warp-per-row, coalesced) ----------
    for (int rr = 0; rr < M_TILE / WARPS; ++rr) {
        const int r = w * (M_TILE / WARPS) + rr;
        const float4* x4 = reinterpret_cast<const float4*>(
            X + (size_t)(rowbase + r) * DDIM);
        const float4 xa = x4[lane * 2], xb = x4[lane * 2 + 1];
        const float thresh = sRowMax[r] - MARGIN;

        float v1 = FLT_MAX, v2 = FLT_MAX;
        int   i1 = INT_MAX, i2 = INT_MAX;
#pragma unroll 1
        for (int c = 0; c < 24; ++c) {
            const uint32_t pk = sCand[r][c];        // smem broadcast (uniform)
            if (dec_score(pk) < thresh) continue;   // pruned: ~22 of 24 avg
            const int cand = (int)(pk & 1023u);
            const float4* e4 = reinterpret_cast<const float4*>(
                E + (size_t)cand * DDIM);
            const float4 ea = e4[lane * 2], eb = e4[lane * 2 + 1];
            float d, dd = 0.0f;
            d = xa.x - ea.x; dd += d * d;  d = xa.y - ea.y; dd += d * d;
            d = xa.z - ea.z; dd += d * d;  d = xa.w - ea.w; dd += d * d;
            d = xb.x - eb.x; dd += d * d;  d = xb.y - eb.y; dd += d * d;
            d = xb.z - eb.z; dd += d * d;  d = xb.w - eb.w; dd += d * d;
#pragma unroll
            for (int o = 16; o >= 1; o >>= 1)
                dd += __shfl_xor_sync(0xffffffffu, dd, o);
            top2min(dd, cand, v1, i1, v2, i2);
        }
        if (i2 == INT_MAX) i2 = i1;   // only one survivor

        // exact fp64 on the two finalists (coalesced, warp-reduced)
        const float4* ea4 = reinterpret_cast<const float4*>(E + (size_t)i1 * DDIM);
        const float4* eb4 = reinterpret_cast<const float4*>(E + (size_t)i2 * DDIM);
        const float4 a0 = ea4[lane * 2], a1 = ea4[lane * 2 + 1];
        const float4 b0 = eb4[lane * 2], b1 = eb4[lane * 2 + 1];
        double dd, dA = 0.0, dB = 0.0;
        dd = (double)xa.x - (double)a0.x; dA += dd * dd;
        dd = (double)xa.y - (double)a0.y; dA += dd * dd;
        dd = (double)xa.z - (double)a0.z; dA += dd * dd;
        dd = (double)xa.w - (double)a0.w; dA += dd * dd;
        dd = (double)xb.x - (double)a1.x; dA += dd * dd;
        dd = (double)xb.y - (double)a1.y; dA += dd * dd;
        dd = (double)xb.z - (double)a1.z; dA += dd * dd;
        dd = (double)xb.w - (double)a1.w; dA += dd * dd;
        dd = (double)xa.x - (double)b0.x; dB += dd * dd;
        dd = (double)xa.y - (double)b0.y; dB += dd * dd;
        dd = (double)xa.z - (double)b0.z; dB += dd * dd;
        dd = (double)xa.w - (double)b0.w; dB += dd * dd;
        dd = (double)xb.x - (double)b1.x; dB += dd * dd;
        dd = (double)xb.y - (double)b1.y; dB += dd * dd;
        dd = (double)xb.z - (double)b1.z; dB += dd * dd;
        dd = (double)xb.w - (double)b1.w; dB += dd * dd;
#pragma unroll
        for (int o = 16; o >= 1; o >>= 1) {
            dA += __shfl_xor_sync(0xffffffffu, dA, o);
            dB += __shfl_xor_sync(0xffffffffu, dB, o);
        }
        int win = (dA < dB || (dA == dB && i1 < i2)) ? i1 : i2;
        if (lane == 0) sWin[r] = win;
    }
    __syncthreads();

    // ---- epilogue: striped gather + straight-through + loss (R15 form) ----
    float lsum = 0.0f;
    {
        const float4* xg = reinterpret_cast<const float4*>(X + (size_t)rowbase * DDIM);
        for (int i = tid; i < M_TILE * (DDIM / 4); i += THREADS) {
            int r = i >> 6, c4 = i & 63;
            int idx = sWin[r];
            float4 e = *reinterpret_cast<const float4*>(E + (size_t)idx * DDIM + c4 * 4);
            float4 x = xg[i];
            float4 d, q;
            d.x = e.x - x.x; d.y = e.y - x.y; d.z = e.z - x.z; d.w = e.w - x.w;
            q.x = x.x + d.x; q.y = x.y + d.y; q.z = x.z + d.z; q.w = x.w + d.w;
            lsum += d.x * d.x + d.y * d.y + d.z * d.z + d.w * d.w;
            *reinterpret_cast<float4*>(outQ + (size_t)(rowbase + r) * DDIM + c4 * 4) = q;
        }
    }
    if (tid < M_TILE) outIdx[rowbase + tid] = (float)sWin[tid];

#pragma unroll
    for (int s = 16; s >= 1; s >>= 1)
        lsum += __shfl_xor_sync(0xffffffffu, lsum, s);
    if (lane == 0) sRed[w] = lsum;
    __syncthreads();
    if (tid == 0) {
        float s = 0.0f;
#pragma unroll
        for (int i = 0; i < WARPS; ++i) s += sRed[i];
        atomicAdd(&g_loss_accum, (double)s);
    }
}

// ---------------------------------------------------------------------------
__global__ void vq_finalize(float* __restrict__ outLoss) {
    if (threadIdx.x == 0)
        *outLoss = (float)(g_loss_accum * (1.0 / (double)((size_t)NROWS * DDIM)));
}

// ---------------------------------------------------------------------------
extern "C" void kernel_launch(void* const* d_in, const int* in_sizes, int n_in,
                              void* d_out, int out_size) {
    (void)in_sizes; (void)n_in; (void)out_size;
    const float* X = (const float*)d_in[0];
    const float* E = (const float*)d_in[1];

    float* outQ    = (float*)d_out;
    float* outLoss = outQ + (size_t)NROWS * DDIM;   // 16777216
    float* outIdx  = outLoss + 1;                   // 16777217

    cudaFuncSetAttribute(vq_main_mma, cudaFuncAttributeMaxDynamicSharedMemorySize,
                         DYN_SMEM);

    vq_prep<<<KCODES / 8, 256>>>(E);
    vq_main_mma<<<NROWS / M_TILE, THREADS, DYN_SMEM>>>(X, E, outQ, outIdx);
    vq_finalize<<<1, 32>>>(outLoss);
}